// round 2
// baseline (speedup 1.0000x reference)
#include <cuda_runtime.h>
#include <math.h>

#define B 256
#define T 512
#define F 128
#define H 256
#define H3 768

// Static device scratch for the hoisted input projection: MX[t*B+b][0..767]
__device__ float g_mx[(size_t)T * B * H3];   // ~402 MB, allowed (static __device__)

// ---------------------------------------------------------------------------
// Kernel 1: MX[m, n] = x[b, t, :] @ W[:, n] + bias_in[n],  m = t*B + b
// Tiled fp32 GEMM: 64x64 tile, BK=32, 256 threads, 4x4 microtile.
// ---------------------------------------------------------------------------
#define GM_BM 64
#define GM_BN 64
#define GM_BK 32

__global__ __launch_bounds__(256) void mx_gemm(const float* __restrict__ x,
                                               const float* __restrict__ w,
                                               const float* __restrict__ bias) {
    __shared__ float As[GM_BK][GM_BM + 4];   // [k][m], padded
    __shared__ float Bs[GM_BK][GM_BN];       // [k][n]

    const int bm = blockIdx.y * GM_BM;
    const int bn = blockIdx.x * GM_BN;
    const int tid = (int)threadIdx.x;
    const int tm = (tid >> 4) << 2;          // 0..60
    const int tn = (tid & 15) << 2;          // 0..60

    float acc[4][4] = {};

    for (int k0 = 0; k0 < F; k0 += GM_BK) {
        // Load A tile: 64 rows x 32 k, float4 along k, store transposed.
        #pragma unroll
        for (int i = 0; i < 2; i++) {
            int idx = tid + i * 256;         // 0..511
            int r = idx >> 3;                // 0..63
            int c = (idx & 7) << 2;          // 0,4,...,28
            int m = bm + r;
            int t = m >> 8;                  // m / B  (B = 256)
            int b = m & 255;                 // m % B
            float4 v = *(const float4*)&x[((size_t)b * T + t) * F + k0 + c];
            As[c + 0][r] = v.x;
            As[c + 1][r] = v.y;
            As[c + 2][r] = v.z;
            As[c + 3][r] = v.w;
        }
        // Load B tile: 32 k x 64 n.
        #pragma unroll
        for (int i = 0; i < 2; i++) {
            int idx = tid + i * 256;
            int r = idx >> 4;                // 0..31
            int c = (idx & 15) << 2;         // 0..60
            *(float4*)&Bs[r][c] = *(const float4*)&w[(size_t)(k0 + r) * H3 + bn + c];
        }
        __syncthreads();

        #pragma unroll
        for (int k = 0; k < GM_BK; k++) {
            float a0 = As[k][tm + 0];
            float a1 = As[k][tm + 1];
            float a2 = As[k][tm + 2];
            float a3 = As[k][tm + 3];
            float4 bv = *(const float4*)&Bs[k][tn];
            acc[0][0] += a0 * bv.x; acc[0][1] += a0 * bv.y; acc[0][2] += a0 * bv.z; acc[0][3] += a0 * bv.w;
            acc[1][0] += a1 * bv.x; acc[1][1] += a1 * bv.y; acc[1][2] += a1 * bv.z; acc[1][3] += a1 * bv.w;
            acc[2][0] += a2 * bv.x; acc[2][1] += a2 * bv.y; acc[2][2] += a2 * bv.z; acc[2][3] += a2 * bv.w;
            acc[3][0] += a3 * bv.x; acc[3][1] += a3 * bv.y; acc[3][2] += a3 * bv.z; acc[3][3] += a3 * bv.w;
        }
        __syncthreads();
    }

    const float bz0 = bias[bn + tn + 0];
    const float bz1 = bias[bn + tn + 1];
    const float bz2 = bias[bn + tn + 2];
    const float bz3 = bias[bn + tn + 3];
    #pragma unroll
    for (int i = 0; i < 4; i++) {
        float4 o;
        o.x = acc[i][0] + bz0;
        o.y = acc[i][1] + bz1;
        o.z = acc[i][2] + bz2;
        o.w = acc[i][3] + bz3;
        *(float4*)&g_mx[(size_t)(bm + tm + i) * H3 + bn + tn] = o;
    }
}

// ---------------------------------------------------------------------------
// Kernel 2: one GRU step.
//   mh = hprev @ Wr (+ rec_bias applied in epilogue)
//   z = sigmoid(mxz + mhz); r = sigmoid(mxr + mhr); c = tanh(mxh + r*mhh)
//   hout = z*hprev + (1-z)*c
// Tile: 16 batch x 32 hidden per block, 128 threads (1b x 4j per thread).
// Grid: (H/32=8, B/16=16) = 128 blocks.
// hprev == nullptr means h = 0 (step 0).
// ---------------------------------------------------------------------------
#define SB 16
#define SJ 32
#define SK 32

__device__ __forceinline__ float sigmoidf_(float v) {
    return 1.0f / (1.0f + __expf(-v));
}

__global__ __launch_bounds__(128) void gru_step(const float* __restrict__ hprev,
                                                const float* __restrict__ mx_t,
                                                const float* __restrict__ wr,
                                                const float* __restrict__ rbias,
                                                float* __restrict__ hout) {
    __shared__ float hs[SB][SK + 4];         // [b][k], padded (stride 36: 4-bank skew, 16B aligned)
    __shared__ float ws[3][SK][SJ];          // [gate][k][j]

    const int tid = (int)threadIdx.x;        // 0..127
    const int b0 = blockIdx.y * SB;
    const int j0 = blockIdx.x * SJ;
    const int bq = tid >> 3;                 // 0..15
    const int jq = (tid & 7) << 2;           // 0,4,...,28

    float accz[4] = {}, accr[4] = {}, acch[4] = {};

    for (int k0 = 0; k0 < H; k0 += SK) {
        // Load h tile: 16 x 32 floats, 1 float4 per thread.
        {
            int r = tid >> 3;                // 0..15
            int c = (tid & 7) << 2;          // 0..28
            float4 v;
            if (hprev) {
                v = *(const float4*)&hprev[(size_t)(b0 + r) * H + k0 + c];
            } else {
                v = make_float4(0.f, 0.f, 0.f, 0.f);
            }
            *(float4*)&hs[r][c] = v;
        }
        // Load Wr tiles for 3 gates: 3 * 32 * 32 floats = 768 float4, 6 per thread.
        #pragma unroll
        for (int i = 0; i < 6; i++) {
            int idx = tid + i * 128;         // 0..767
            int g = idx >> 8;                // 0..2
            int rem = idx & 255;
            int r = rem >> 3;                // k 0..31
            int c = (rem & 7) << 2;          // j 0..28
            *(float4*)&ws[g][r][c] =
                *(const float4*)&wr[(size_t)(k0 + r) * H3 + g * H + j0 + c];
        }
        __syncthreads();

        #pragma unroll
        for (int k = 0; k < SK; k++) {
            float hv = hs[bq][k];
            float4 wz = *(const float4*)&ws[0][k][jq];
            float4 wv = *(const float4*)&ws[1][k][jq];
            float4 wh = *(const float4*)&ws[2][k][jq];
            accz[0] += hv * wz.x; accz[1] += hv * wz.y; accz[2] += hv * wz.z; accz[3] += hv * wz.w;
            accr[0] += hv * wv.x; accr[1] += hv * wv.y; accr[2] += hv * wv.z; accr[3] += hv * wv.w;
            acch[0] += hv * wh.x; acch[1] += hv * wh.y; acch[2] += hv * wh.z; acch[3] += hv * wh.w;
        }
        __syncthreads();
    }

    const int b = b0 + bq;
    const int j = j0 + jq;
    // mx row for this batch element
    const float* mxr = mx_t + (size_t)b * H3;

    float4 xz = *(const float4*)&mxr[j];
    float4 xr = *(const float4*)&mxr[H + j];
    float4 xh = *(const float4*)&mxr[2 * H + j];
    float4 bzv = *(const float4*)&rbias[j];
    float4 brv = *(const float4*)&rbias[H + j];
    float4 bhv = *(const float4*)&rbias[2 * H + j];

    float hp[4];
    if (hprev) {
        float4 hv = *(const float4*)&hprev[(size_t)b * H + j];
        hp[0] = hv.x; hp[1] = hv.y; hp[2] = hv.z; hp[3] = hv.w;
    } else {
        hp[0] = hp[1] = hp[2] = hp[3] = 0.f;
    }

    float xzv[4] = {xz.x, xz.y, xz.z, xz.w};
    float xrv[4] = {xr.x, xr.y, xr.z, xr.w};
    float xhv[4] = {xh.x, xh.y, xh.z, xh.w};
    float bz[4] = {bzv.x, bzv.y, bzv.z, bzv.w};
    float br[4] = {brv.x, brv.y, brv.z, brv.w};
    float bh[4] = {bhv.x, bhv.y, bhv.z, bhv.w};

    float4 o;
    float out4[4];
    #pragma unroll
    for (int jj = 0; jj < 4; jj++) {
        float z = sigmoidf_(xzv[jj] + accz[jj] + bz[jj]);
        float r = sigmoidf_(xrv[jj] + accr[jj] + br[jj]);
        float hh = acch[jj] + bh[jj];
        float c = tanhf(xhv[jj] + r * hh);
        out4[jj] = z * hp[jj] + (1.0f - z) * c;
    }
    o.x = out4[0]; o.y = out4[1]; o.z = out4[2]; o.w = out4[3];
    *(float4*)&hout[(size_t)b * H + j] = o;
}

// ---------------------------------------------------------------------------
// Launch: one GEMM + 512 chained step kernels (graph-capturable).
// Step t writes its hidden state directly into the output slice out[t];
// step t+1 reads it back as hprev. out layout: (T, B, H).
// ---------------------------------------------------------------------------
extern "C" void kernel_launch(void* const* d_in, const int* in_sizes, int n_in,
                              void* d_out, int out_size) {
    (void)in_sizes; (void)n_in; (void)out_size;
    const float* x    = (const float*)d_in[0];   // (B, T, F)
    const float* w    = (const float*)d_in[1];   // (F, 3H)
    const float* wr   = (const float*)d_in[2];   // (H, 3H)
    const float* bias = (const float*)d_in[3];   // (2, 3H)
    float* out = (float*)d_out;                  // (T, B, H)

    float* mx;
    cudaGetSymbolAddress((void**)&mx, g_mx);

    dim3 g1(H3 / GM_BN, (T * B) / GM_BM);        // (12, 2048)
    mx_gemm<<<g1, 256>>>(x, w, bias);

    const float* rbias = bias + H3;              // recurrent bias
    dim3 g2(H / SJ, B / SB);                     // (8, 16) = 128 blocks

    for (int t = 0; t < T; t++) {
        const float* hprev = (t == 0) ? nullptr : out + (size_t)(t - 1) * B * H;
        gru_step<<<g2, 128>>>(hprev,
                              mx + (size_t)t * B * H3,
                              wr,
                              rbias,
                              out + (size_t)t * B * H);
    }
}

// round 3
// speedup vs baseline: 1.6302x; 1.6302x over previous
#include <cuda_runtime.h>
#include <math.h>

#define B 256
#define T 512
#define F 128
#define H 256
#define H3 768
#define BH (B * H)

// Static device scratch for the hoisted input projection: MX[t*B+b][0..767]
__device__ float g_mx[(size_t)T * B * H3];   // ~402 MB

// Flag array for inter-block sync (one 128B line per flag)
#define NJB 8
#define NBB 16
__device__ unsigned g_flags[NBB][NJB * 32];

// ---------------------------------------------------------------------------
// f32x2 packed-FMA helpers (FFMA2 — only reachable via PTX fma.rn.f32x2)
// ---------------------------------------------------------------------------
__device__ __forceinline__ void ffma2(unsigned long long &acc,
                                      unsigned long long a,
                                      unsigned long long b) {
    asm("fma.rn.f32x2 %0, %1, %2, %0;" : "+l"(acc) : "l"(a), "l"(b));
}
__device__ __forceinline__ unsigned long long dup2(float v) {
    unsigned long long r;
    asm("mov.b64 %0, {%1, %1};" : "=l"(r) : "f"(v));
    return r;
}
__device__ __forceinline__ float2 unpk(unsigned long long v) {
    float2 r;
    asm("mov.b64 {%0, %1}, %2;" : "=f"(r.x), "=f"(r.y) : "l"(v));
    return r;
}
__device__ __forceinline__ float sigmoidf_(float v) {
    return 1.0f / (1.0f + __expf(-v));
}

// ---------------------------------------------------------------------------
// Kernel 1: MX[m, n] = x[b, t, :] @ W[:, n] + bias_in[n],  m = t*B + b
// 64x64 tile, BK=32, 256 threads, 4x4 microtile, f32x2 FMAs.
// ---------------------------------------------------------------------------
#define GM_BM 64
#define GM_BN 64
#define GM_BK 32

__global__ __launch_bounds__(256) void mx_gemm(const float* __restrict__ x,
                                               const float* __restrict__ w,
                                               const float* __restrict__ bias) {
    __shared__ float As[GM_BK][GM_BM + 4];   // [k][m], padded
    __shared__ float Bs[GM_BK][GM_BN];       // [k][n]

    const int bm = blockIdx.y * GM_BM;
    const int bn = blockIdx.x * GM_BN;
    const int tid = (int)threadIdx.x;
    const int tm = (tid >> 4) << 2;          // 0..60
    const int tn = (tid & 15) << 2;          // 0..60

    unsigned long long acc2[4][2];
    #pragma unroll
    for (int i = 0; i < 4; i++) { acc2[i][0] = 0ull; acc2[i][1] = 0ull; }

    for (int k0 = 0; k0 < F; k0 += GM_BK) {
        #pragma unroll
        for (int i = 0; i < 2; i++) {
            int idx = tid + i * 256;         // 0..511
            int r = idx >> 3;                // 0..63
            int c = (idx & 7) << 2;          // 0,4,...,28
            int m = bm + r;
            int t = m >> 8;                  // m / B
            int b = m & 255;                 // m % B
            float4 v = *(const float4*)&x[((size_t)b * T + t) * F + k0 + c];
            As[c + 0][r] = v.x;
            As[c + 1][r] = v.y;
            As[c + 2][r] = v.z;
            As[c + 3][r] = v.w;
        }
        #pragma unroll
        for (int i = 0; i < 2; i++) {
            int idx = tid + i * 256;
            int r = idx >> 4;                // 0..31
            int c = (idx & 15) << 2;         // 0..60
            *(float4*)&Bs[r][c] = *(const float4*)&w[(size_t)(k0 + r) * H3 + bn + c];
        }
        __syncthreads();

        #pragma unroll
        for (int k = 0; k < GM_BK; k++) {
            unsigned long long a0 = dup2(As[k][tm + 0]);
            unsigned long long a1 = dup2(As[k][tm + 1]);
            unsigned long long a2 = dup2(As[k][tm + 2]);
            unsigned long long a3 = dup2(As[k][tm + 3]);
            const unsigned long long* bsk = (const unsigned long long*)&Bs[k][tn];
            unsigned long long b01 = bsk[0];
            unsigned long long b23 = bsk[1];
            ffma2(acc2[0][0], a0, b01); ffma2(acc2[0][1], a0, b23);
            ffma2(acc2[1][0], a1, b01); ffma2(acc2[1][1], a1, b23);
            ffma2(acc2[2][0], a2, b01); ffma2(acc2[2][1], a2, b23);
            ffma2(acc2[3][0], a3, b01); ffma2(acc2[3][1], a3, b23);
        }
        __syncthreads();
    }

    float4 bz4 = *(const float4*)&bias[bn + tn];
    #pragma unroll
    for (int i = 0; i < 4; i++) {
        float2 lo = unpk(acc2[i][0]);
        float2 hi = unpk(acc2[i][1]);
        float4 o;
        o.x = lo.x + bz4.x;
        o.y = lo.y + bz4.y;
        o.z = hi.x + bz4.z;
        o.w = hi.y + bz4.w;
        *(float4*)&g_mx[(size_t)(bm + tm + i) * H3 + bn + tn] = o;
    }
}

// ---------------------------------------------------------------------------
// Kernel 2: persistent GRU recurrence.
// Grid (8 j-tiles, 16 b-tiles) = 128 blocks, 128 threads, 1 block/SM.
// Each block owns a (16 batch x 32 hidden) output tile for all 512 steps.
// Wr slice (256 k x 96 gate-cols = 98KB) cached in smem ONCE.
// Per-step sync: only the 8 blocks sharing a batch tile need each other's
// h writes -> 8-flag spin barrier per row group. No cooperative launch.
// ---------------------------------------------------------------------------
#define BT 16            // batch rows per block
#define JT 32            // hidden cols per block (x3 gates)
#define WS_FLOATS (256 * 96)
#define HSS 264          // h tile row stride (floats)
#define SMEM_BYTES ((WS_FLOATS + BT * HSS) * 4)

extern __shared__ float smem_dyn[];

__global__ __launch_bounds__(128, 1) void gru_persist(const float* __restrict__ mx,
                                                      const float* __restrict__ wr,
                                                      const float* __restrict__ rbias,
                                                      float* __restrict__ out) {
    float* ws = smem_dyn;                     // [k=256][96]  (3 gates x 32 j)
    float* hs = smem_dyn + WS_FLOATS;         // [b=16][HSS]

    const int tid = (int)threadIdx.x;         // 0..127
    const int jb = (int)blockIdx.x;           // 0..7
    const int ib = (int)blockIdx.y;           // 0..15
    const int b0 = ib * BT;
    const int j0 = jb * JT;
    const int jp = tid & 15;                  // j-pair index 0..15
    const int bq = tid >> 4;                  // 0..7 -> handles b rows 2bq, 2bq+1
    const int j = j0 + 2 * jp;

    // Load Wr slice once: ws[k][g*32+jj] = wr[k][g*256 + j0 + jj]
    for (int idx = tid; idx < WS_FLOATS / 2; idx += 128) {
        int k = idx / 48;
        int c2 = idx % 48;                    // column pair
        int g = c2 >> 4;
        int jj = (c2 & 15) << 1;
        float2 v = *(const float2*)&wr[(size_t)k * H3 + g * H + j0 + jj];
        *(float2*)&ws[k * 96 + g * 32 + jj] = v;
    }

    // Recurrent bias for this thread's 2 j columns (constant over t)
    float2 bzv = *(const float2*)&rbias[j];
    float2 brv = *(const float2*)&rbias[H + j];
    float2 bhv = *(const float2*)&rbias[2 * H + j];
    __syncthreads();

    for (int t = 0; t < T; t++) {
        // ---- wait for the 8 peer blocks of this batch row group ----
        if (t > 0) {
            if (tid < NJB) {
                volatile unsigned* f = &g_flags[ib][tid * 32];
                while (*f < (unsigned)t) { __nanosleep(32); }
            }
            __syncthreads();
            // ---- stage h_prev tile (16 x 256) into smem ----
            const float* hsrc = out + (size_t)(t - 1) * BH;
            #pragma unroll
            for (int i = 0; i < 8; i++) {
                int idx = tid + i * 128;      // 0..1023
                int r = idx >> 6;             // 0..15
                int c = (idx & 63) << 2;      // 0..252
                float4 v = *(const float4*)&hsrc[(size_t)(b0 + r) * H + c];
                *(float4*)&hs[r * HSS + c] = v;
            }
        } else {
            #pragma unroll
            for (int i = 0; i < 8; i++) {
                int idx = tid + i * 128;
                int r = idx >> 6;
                int c = (idx & 63) << 2;
                *(float4*)&hs[r * HSS + c] = make_float4(0.f, 0.f, 0.f, 0.f);
            }
        }
        __syncthreads();

        // ---- mh = h @ Wr for this tile (f32x2 packed FMAs) ----
        unsigned long long az[2] = {0ull, 0ull};
        unsigned long long ar[2] = {0ull, 0ull};
        unsigned long long ah[2] = {0ull, 0ull};
        const float* h0p = hs + (2 * bq) * HSS;
        const float* h1p = hs + (2 * bq + 1) * HSS;

        #pragma unroll 8
        for (int k = 0; k < H; k++) {
            const unsigned long long* wsk = (const unsigned long long*)(ws + k * 96);
            unsigned long long wz = wsk[jp];
            unsigned long long wv = wsk[16 + jp];
            unsigned long long wh = wsk[32 + jp];
            unsigned long long h0d = dup2(h0p[k]);
            unsigned long long h1d = dup2(h1p[k]);
            ffma2(az[0], h0d, wz); ffma2(ar[0], h0d, wv); ffma2(ah[0], h0d, wh);
            ffma2(az[1], h1d, wz); ffma2(ar[1], h1d, wv); ffma2(ah[1], h1d, wh);
        }

        // ---- gates + output ----
        const float* mxt = mx + (size_t)t * B * H3;
        float* outt = out + (size_t)t * BH;
        #pragma unroll
        for (int bb = 0; bb < 2; bb++) {
            int b = b0 + 2 * bq + bb;
            const float* mxr = mxt + (size_t)b * H3 + j;
            float2 xz = *(const float2*)(mxr);
            float2 xr = *(const float2*)(mxr + H);
            float2 xh = *(const float2*)(mxr + 2 * H);
            float2 a_z = unpk(az[bb]);
            float2 a_r = unpk(ar[bb]);
            float2 a_h = unpk(ah[bb]);
            const float* hrow = hs + (2 * bq + bb) * HSS;
            float hp0 = hrow[j];
            float hp1 = hrow[j + 1];

            float z0 = sigmoidf_(xz.x + a_z.x + bzv.x);
            float z1 = sigmoidf_(xz.y + a_z.y + bzv.y);
            float r0 = sigmoidf_(xr.x + a_r.x + brv.x);
            float r1 = sigmoidf_(xr.y + a_r.y + brv.y);
            float c0 = tanhf(xh.x + r0 * (a_h.x + bhv.x));
            float c1 = tanhf(xh.y + r1 * (a_h.y + bhv.y));
            float2 o;
            o.x = z0 * hp0 + (1.0f - z0) * c0;
            o.y = z1 * hp1 + (1.0f - z1) * c1;
            *(float2*)&outt[(size_t)b * H + j] = o;
        }

        // ---- publish: all writes visible, then raise our flag ----
        __threadfence();
        __syncthreads();
        if (tid == 0) {
            *(volatile unsigned*)&g_flags[ib][jb * 32] = (unsigned)(t + 1);
        }
    }
}

// ---------------------------------------------------------------------------
// Launch: flag memset + input-projection GEMM + one persistent kernel.
// ---------------------------------------------------------------------------
extern "C" void kernel_launch(void* const* d_in, const int* in_sizes, int n_in,
                              void* d_out, int out_size) {
    (void)in_sizes; (void)n_in; (void)out_size;
    const float* x    = (const float*)d_in[0];   // (B, T, F)
    const float* w    = (const float*)d_in[1];   // (F, 3H)
    const float* wr   = (const float*)d_in[2];   // (H, 3H)
    const float* bias = (const float*)d_in[3];   // (2, 3H)
    float* out = (float*)d_out;                  // (T, B, H)

    static int attr_set = 0;
    if (!attr_set) {
        cudaFuncSetAttribute(gru_persist,
                             cudaFuncAttributeMaxDynamicSharedMemorySize,
                             SMEM_BYTES);
        attr_set = 1;
    }

    float* mx;
    cudaGetSymbolAddress((void**)&mx, g_mx);
    void* flags;
    cudaGetSymbolAddress(&flags, g_flags);

    // Reset sync flags (graph-replay safe)
    cudaMemsetAsync(flags, 0, sizeof(unsigned) * NBB * NJB * 32, 0);

    // Hoisted input projection
    dim3 g1(H3 / GM_BN, (T * B) / GM_BM);        // (12, 2048)
    mx_gemm<<<g1, 256>>>(x, w, bias);

    // Persistent recurrence
    const float* rbias = bias + H3;
    dim3 g2(NJB, NBB);                           // (8, 16) = 128 blocks
    gru_persist<<<g2, 128, SMEM_BYTES>>>(mx, wr, rbias, out);
}

// round 4
// speedup vs baseline: 2.1583x; 1.3239x over previous
#include <cuda_runtime.h>
#include <math.h>

#define B 256
#define T 512
#define F 128
#define H 256
#define H3 768
#define BH (B * H)

// Static device scratch for the hoisted input projection: MX[t*B+b][0..767]
__device__ float g_mx[(size_t)T * B * H3];   // ~402 MB

// Flag array for inter-block sync (one 128B line per flag)
#define NJB 8
#define NBB 16
__device__ unsigned g_flags[NBB][NJB * 32];

// ---------------------------------------------------------------------------
// f32x2 packed-FMA helpers (FFMA2 — only reachable via PTX fma.rn.f32x2)
// ---------------------------------------------------------------------------
__device__ __forceinline__ void ffma2(unsigned long long &acc,
                                      unsigned long long a,
                                      unsigned long long b) {
    asm("fma.rn.f32x2 %0, %1, %2, %0;" : "+l"(acc) : "l"(a), "l"(b));
}
__device__ __forceinline__ unsigned long long dup2(float v) {
    unsigned long long r;
    asm("mov.b64 %0, {%1, %1};" : "=l"(r) : "f"(v));
    return r;
}
__device__ __forceinline__ float2 unpk(unsigned long long v) {
    float2 r;
    asm("mov.b64 {%0, %1}, %2;" : "=f"(r.x), "=f"(r.y) : "l"(v));
    return r;
}
__device__ __forceinline__ float tanh_fast(float x) {
    float y;
    asm("tanh.approx.f32 %0, %1;" : "=f"(y) : "f"(x));
    return y;
}
__device__ __forceinline__ float sig_fast(float x) {
    return fmaf(0.5f, tanh_fast(0.5f * x), 0.5f);
}

// ---------------------------------------------------------------------------
// Kernel 1: MX[m, n] = x[b, t, :] @ W[:, n] + bias_in[n],  m = t*B + b
// 64x64 tile, BK=32, 256 threads, 4x4 microtile, f32x2 FMAs.
// ---------------------------------------------------------------------------
#define GM_BM 64
#define GM_BN 64
#define GM_BK 32

__global__ __launch_bounds__(256) void mx_gemm(const float* __restrict__ x,
                                               const float* __restrict__ w,
                                               const float* __restrict__ bias) {
    __shared__ float As[GM_BK][GM_BM + 4];   // [k][m], padded
    __shared__ float Bs[GM_BK][GM_BN];       // [k][n]

    const int bm = blockIdx.y * GM_BM;
    const int bn = blockIdx.x * GM_BN;
    const int tid = (int)threadIdx.x;
    const int tm = (tid >> 4) << 2;          // 0..60
    const int tn = (tid & 15) << 2;          // 0..60

    unsigned long long acc2[4][2];
    #pragma unroll
    for (int i = 0; i < 4; i++) { acc2[i][0] = 0ull; acc2[i][1] = 0ull; }

    for (int k0 = 0; k0 < F; k0 += GM_BK) {
        #pragma unroll
        for (int i = 0; i < 2; i++) {
            int idx = tid + i * 256;         // 0..511
            int r = idx >> 3;                // 0..63
            int c = (idx & 7) << 2;          // 0,4,...,28
            int m = bm + r;
            int t = m >> 8;                  // m / B
            int b = m & 255;                 // m % B
            float4 v = *(const float4*)&x[((size_t)b * T + t) * F + k0 + c];
            As[c + 0][r] = v.x;
            As[c + 1][r] = v.y;
            As[c + 2][r] = v.z;
            As[c + 3][r] = v.w;
        }
        #pragma unroll
        for (int i = 0; i < 2; i++) {
            int idx = tid + i * 256;
            int r = idx >> 4;                // 0..31
            int c = (idx & 15) << 2;         // 0..60
            *(float4*)&Bs[r][c] = *(const float4*)&w[(size_t)(k0 + r) * H3 + bn + c];
        }
        __syncthreads();

        #pragma unroll
        for (int k = 0; k < GM_BK; k++) {
            unsigned long long a0 = dup2(As[k][tm + 0]);
            unsigned long long a1 = dup2(As[k][tm + 1]);
            unsigned long long a2 = dup2(As[k][tm + 2]);
            unsigned long long a3 = dup2(As[k][tm + 3]);
            const unsigned long long* bsk = (const unsigned long long*)&Bs[k][tn];
            unsigned long long b01 = bsk[0];
            unsigned long long b23 = bsk[1];
            ffma2(acc2[0][0], a0, b01); ffma2(acc2[0][1], a0, b23);
            ffma2(acc2[1][0], a1, b01); ffma2(acc2[1][1], a1, b23);
            ffma2(acc2[2][0], a2, b01); ffma2(acc2[2][1], a2, b23);
            ffma2(acc2[3][0], a3, b01); ffma2(acc2[3][1], a3, b23);
        }
        __syncthreads();
    }

    float4 bz4 = *(const float4*)&bias[bn + tn];
    #pragma unroll
    for (int i = 0; i < 4; i++) {
        float2 lo = unpk(acc2[i][0]);
        float2 hi = unpk(acc2[i][1]);
        float4 o;
        o.x = lo.x + bz4.x;
        o.y = lo.y + bz4.y;
        o.z = hi.x + bz4.z;
        o.w = hi.y + bz4.w;
        *(float4*)&g_mx[(size_t)(bm + tm + i) * H3 + bn + tn] = o;
    }
}

// ---------------------------------------------------------------------------
// Kernel 2: persistent GRU recurrence (k-split version).
// Grid (8 j-tiles, 16 b-tiles) = 128 blocks, 256 threads, 1 block/SM.
// Block owns a (16 batch x 32 hidden) output tile for all 512 steps.
// Wr slice (256 k x 96 gate-cols = 98KB) cached in smem once.
// Per step:
//   phase A: 4 k-groups (64 threads each) compute partial mh over 64 k's;
//            microtile per thread = 2 b-rows x 4 j-cols x 3 gates (12 FFMA2/k)
//   phase B/C: reduce 4 partials from smem, apply gates, store h.
// Sync across the 8 blocks sharing a batch tile via flags in global.
// ---------------------------------------------------------------------------
#define BT 16            // batch rows per block
#define JT 32            // hidden cols per block (x3 gates)
#define WS_FLOATS (256 * 96)
#define HSS 260          // h tile row stride (260 mod 32 = 4 -> bank skew)
#define HS_FLOATS (BT * HSS)
#define PT_FLOATS (4 * BT * 96)
#define SMEM_BYTES ((WS_FLOATS + HS_FLOATS + PT_FLOATS) * 4)

extern __shared__ float smem_dyn[];

__global__ __launch_bounds__(256, 1) void gru_persist(const float* __restrict__ mx,
                                                      const float* __restrict__ wr,
                                                      const float* __restrict__ rbias,
                                                      float* __restrict__ out) {
    float* ws = smem_dyn;                       // [k=256][96]
    float* hs = ws + WS_FLOATS;                 // [b=16][HSS]
    float* pt = hs + HS_FLOATS;                 // [kg=4][b=16][96]

    const int tid = (int)threadIdx.x;           // 0..255
    const int jb = (int)blockIdx.x;             // 0..7
    const int ib = (int)blockIdx.y;             // 0..15
    const int b0 = ib * BT;
    const int j0 = jb * JT;

    // Phase-A mapping
    const int kg = tid >> 6;                    // 0..3
    const int r6 = tid & 63;
    const int bqa = r6 >> 3;                    // 0..7 -> rows 2bqa, 2bqa+1
    const int jqa = (r6 & 7) << 2;              // 0,4,...,28

    // Phase-C mapping
    const int bc = tid >> 4;                    // 0..15
    const int jc = (tid & 15) << 1;             // 0..30

    // Load Wr slice once: ws[k][g*32+jj] = wr[k][g*256 + j0 + jj]
    for (int idx = tid; idx < WS_FLOATS / 2; idx += 256) {
        int k = idx / 48;
        int c2 = idx % 48;
        int g = c2 >> 4;
        int jj = (c2 & 15) << 1;
        float2 v = *(const float2*)&wr[(size_t)k * H3 + g * H + j0 + jj];
        *(float2*)&ws[k * 96 + g * 32 + jj] = v;
    }

    // Recurrent bias for phase-C columns (constant over t)
    float2 bzv = *(const float2*)&rbias[j0 + jc];
    float2 brv = *(const float2*)&rbias[H + j0 + jc];
    float2 bhv = *(const float2*)&rbias[2 * H + j0 + jc];

    // Zero-init hs for t=0
    #pragma unroll
    for (int i = 0; i < 4; i++) {
        int idx = tid + i * 256;
        int r = idx >> 6;
        int c = (idx & 63) << 2;
        *(float4*)&hs[r * HSS + c] = make_float4(0.f, 0.f, 0.f, 0.f);
    }
    __syncthreads();

    for (int t = 0; t < T; t++) {
        // ---- prefetch mx gate inputs for this thread's phase-C outputs ----
        const float* mxr = mx + ((size_t)t * B + (b0 + bc)) * H3 + (j0 + jc);
        float2 xz = *(const float2*)(mxr);
        float2 xr = *(const float2*)(mxr + H);
        float2 xh = *(const float2*)(mxr + 2 * H);

        // ---- wait for the 8 peer blocks of this batch row group ----
        if (t > 0) {
            if (tid < NJB) {
                volatile unsigned* f = &g_flags[ib][tid * 32];
                while (*f < (unsigned)t) { __nanosleep(32); }
            }
            __syncthreads();
            // ---- stage h_prev tile (16 x 256) into smem ----
            const float* hsrc = out + (size_t)(t - 1) * BH;
            #pragma unroll
            for (int i = 0; i < 4; i++) {
                int idx = tid + i * 256;          // 0..1023
                int r = idx >> 6;                 // 0..15
                int c = (idx & 63) << 2;          // 0..252
                float4 v = *(const float4*)&hsrc[(size_t)(b0 + r) * H + c];
                *(float4*)&hs[r * HSS + c] = v;
            }
            __syncthreads();
        }

        // ---- phase A: partial mh over this k-group's 64 k's ----
        unsigned long long acc[2][3][2];
        #pragma unroll
        for (int bb = 0; bb < 2; bb++)
            #pragma unroll
            for (int g = 0; g < 3; g++) {
                acc[bb][g][0] = 0ull; acc[bb][g][1] = 0ull;
            }

        const float* h0p = hs + (2 * bqa) * HSS;
        const float* h1p = hs + (2 * bqa + 1) * HSS;
        const int k_beg = kg * 64;

        #pragma unroll 8
        for (int kk = 0; kk < 64; kk++) {
            int k = k_beg + kk;
            const float* wk = ws + k * 96 + jqa;
            ulonglong2 wz = *(const ulonglong2*)(wk);
            ulonglong2 wv = *(const ulonglong2*)(wk + 32);
            ulonglong2 wh = *(const ulonglong2*)(wk + 64);
            unsigned long long h0 = dup2(h0p[k]);
            unsigned long long h1 = dup2(h1p[k]);
            ffma2(acc[0][0][0], h0, wz.x); ffma2(acc[0][0][1], h0, wz.y);
            ffma2(acc[0][1][0], h0, wv.x); ffma2(acc[0][1][1], h0, wv.y);
            ffma2(acc[0][2][0], h0, wh.x); ffma2(acc[0][2][1], h0, wh.y);
            ffma2(acc[1][0][0], h1, wz.x); ffma2(acc[1][0][1], h1, wz.y);
            ffma2(acc[1][1][0], h1, wv.x); ffma2(acc[1][1][1], h1, wv.y);
            ffma2(acc[1][2][0], h1, wh.x); ffma2(acc[1][2][1], h1, wh.y);
        }

        // store partials: pt[kg][row][g*32 + jqa .. +3]
        #pragma unroll
        for (int bb = 0; bb < 2; bb++) {
            float* pr = pt + ((kg * BT + 2 * bqa + bb) * 96) + jqa;
            #pragma unroll
            for (int g = 0; g < 3; g++) {
                ulonglong2 v;
                v.x = acc[bb][g][0];
                v.y = acc[bb][g][1];
                *(ulonglong2*)(pr + g * 32) = v;
            }
        }
        __syncthreads();

        // ---- phase B/C: reduce partials, gates, output ----
        {
            const float* p0 = pt + (0 * BT + bc) * 96 + jc;
            const float* p1 = pt + (1 * BT + bc) * 96 + jc;
            const float* p2 = pt + (2 * BT + bc) * 96 + jc;
            const float* p3 = pt + (3 * BT + bc) * 96 + jc;

            float2 mzv, mrv, mhv;
            #pragma unroll
            for (int g = 0; g < 3; g++) {
                float2 a = *(const float2*)(p0 + g * 32);
                float2 b = *(const float2*)(p1 + g * 32);
                float2 c = *(const float2*)(p2 + g * 32);
                float2 d = *(const float2*)(p3 + g * 32);
                float2 s;
                s.x = (a.x + b.x) + (c.x + d.x);
                s.y = (a.y + b.y) + (c.y + d.y);
                if (g == 0) mzv = s; else if (g == 1) mrv = s; else mhv = s;
            }

            float hp0 = hs[bc * HSS + j0 + jc];
            float hp1 = hs[bc * HSS + j0 + jc + 1];

            float z0 = sig_fast(xz.x + mzv.x + bzv.x);
            float z1 = sig_fast(xz.y + mzv.y + bzv.y);
            float r0 = sig_fast(xr.x + mrv.x + brv.x);
            float r1 = sig_fast(xr.y + mrv.y + brv.y);
            float c0 = tanh_fast(xh.x + r0 * (mhv.x + bhv.x));
            float c1 = tanh_fast(xh.y + r1 * (mhv.y + bhv.y));
            float2 o;
            o.x = c0 + z0 * (hp0 - c0);
            o.y = c1 + z1 * (hp1 - c1);
            *(float2*)&out[(size_t)t * BH + (size_t)(b0 + bc) * H + j0 + jc] = o;
        }

        // ---- publish ----
        __threadfence();
        __syncthreads();
        if (tid == 0) {
            *(volatile unsigned*)&g_flags[ib][jb * 32] = (unsigned)(t + 1);
        }
    }
}

// ---------------------------------------------------------------------------
// Launch: flag memset + input-projection GEMM + one persistent kernel.
// ---------------------------------------------------------------------------
extern "C" void kernel_launch(void* const* d_in, const int* in_sizes, int n_in,
                              void* d_out, int out_size) {
    (void)in_sizes; (void)n_in; (void)out_size;
    const float* x    = (const float*)d_in[0];   // (B, T, F)
    const float* w    = (const float*)d_in[1];   // (F, 3H)
    const float* wr   = (const float*)d_in[2];   // (H, 3H)
    const float* bias = (const float*)d_in[3];   // (2, 3H)
    float* out = (float*)d_out;                  // (T, B, H)

    static int attr_set = 0;
    if (!attr_set) {
        cudaFuncSetAttribute(gru_persist,
                             cudaFuncAttributeMaxDynamicSharedMemorySize,
                             SMEM_BYTES);
        attr_set = 1;
    }

    float* mx;
    cudaGetSymbolAddress((void**)&mx, g_mx);
    void* flags;
    cudaGetSymbolAddress(&flags, g_flags);

    // Reset sync flags (graph-replay safe)
    cudaMemsetAsync(flags, 0, sizeof(unsigned) * NBB * NJB * 32, 0);

    // Hoisted input projection
    dim3 g1(H3 / GM_BN, (T * B) / GM_BM);        // (12, 2048)
    mx_gemm<<<g1, 256>>>(x, w, bias);

    // Persistent recurrence
    const float* rbias = bias + H3;
    dim3 g2(NJB, NBB);                           // (8, 16) = 128 blocks
    gru_persist<<<g2, 256, SMEM_BYTES>>>(mx, wr, rbias, out);
}